// round 5
// baseline (speedup 1.0000x reference)
#include <cuda_runtime.h>
#include <math.h>

#define C_ 10
#define Q_ 1000
#define R_ 1024
#define N_ 512
#define S_ 10000
#define M_ (C_*Q_)      // 10000 rows in x_tilda
#define TK 16           // k-slab for covariance GEMM

// ---------------- scratch (device globals; no allocation allowed) ----------
__device__ float g_X[M_*R_];          // centered data, 40 MB
__device__ float g_sigma[R_*R_];      // covariance, then (lower) Cholesky L
__device__ float g_mu[C_*R_];
__device__ float g_scores[N_*C_];
__device__ float g_svos[C_*C_];
__device__ float g_vos[C_*R_];
__device__ float g_sq[C_*S_];
__device__ int   g_bestidx[C_];
__device__ int   g_samp[C_*N_];       // ordered sample indices per class
__device__ int   g_kc[C_];
__device__ float g_cls_sum;
__device__ float g_dist_sum;

// ---------------- packed f32x2 helpers (PTX-only FFMA2) ---------------------
__device__ __forceinline__ unsigned long long pack2(float x, float y){
    unsigned long long r; asm("mov.b64 %0,{%1,%2};":"=l"(r):"f"(x),"f"(y)); return r;
}
__device__ __forceinline__ void unpack2(unsigned long long v, float& x, float& y){
    asm("mov.b64 {%0,%1},%2;":"=f"(x),"=f"(y):"l"(v));
}
__device__ __forceinline__ unsigned long long ffma2(unsigned long long a,
                                                    unsigned long long b,
                                                    unsigned long long c){
    unsigned long long d;
    asm("fma.rn.f32x2 %0,%1,%2,%3;":"=l"(d):"l"(a),"l"(b),"l"(c));
    return d;
}

// ---------------- init: zero accumulators (graph replays re-run everything) -
__global__ void k_init(){
    int t = threadIdx.x;
    if (t < C_) g_kc[t] = 0;
    if (t == 30) g_dist_sum = 0.f;
    if (t == 31) g_cls_sum  = 0.f;
}

// ---------------- per-class ordered sample lists ----------------------------
__global__ void k_labelpos(const int* __restrict__ labels){
    int n = threadIdx.x;
    if (n >= N_) return;
    int lab = labels[n];
    int pos = 0;
    for (int m = 0; m < n; m++) pos += (labels[m] == lab) ? 1 : 0;
    g_samp[lab*N_ + pos] = n;
    atomicAdd(&g_kc[lab], 1);
}

// value of post-scatter queue data[c][q][r]
__device__ __forceinline__ float qval(int c, int q, int r,
                                      const float* __restrict__ idd,
                                      const float* __restrict__ box,
                                      int kc, int cnt){
    if (cnt >= Q_){                       // full queue: roll (drop oldest)
        int thr = Q_ - kc;
        if (q < thr) return idd[((size_t)c*Q_ + q + kc)*R_ + r];
        return box[(size_t)g_samp[c*N_ + (q - thr)]*R_ + r];
    } else {                              // filling (unused for this setup)
        if (q >= cnt && q < cnt + kc)
            return box[(size_t)g_samp[c*N_ + (q - cnt)]*R_ + r];
        return idd[((size_t)c*Q_ + q)*R_ + r];
    }
}

// ---------------- per-class mean --------------------------------------------
__global__ void k_mu(const float* __restrict__ idd, const float* __restrict__ box,
                     const int* __restrict__ counter){
    int c = blockIdx.x >> 2;
    int r = ((blockIdx.x & 3) << 8) + threadIdx.x;   // 4 blocks x 256 = 1024 r's
    int kc = g_kc[c], cnt = counter[c];
    float s = 0.f;
    for (int q = 0; q < Q_; q++) s += qval(c, q, r, idd, box, kc, cnt);
    g_mu[c*R_ + r] = s * (1.0f/Q_);
}

// ---------------- centered data X -------------------------------------------
__global__ void k_center(const float* __restrict__ idd, const float* __restrict__ box,
                         const int* __restrict__ counter){
    int idx = blockIdx.x*blockDim.x + threadIdx.x;   // < M_*R_
    int r = idx & (R_-1);
    int m = idx >> 10;
    int c = m / Q_;
    int q = m - c*Q_;
    g_X[idx] = qval(c, q, r, idd, box, g_kc[c], counter[c]) - g_mu[c*R_ + r];
}

// ---------------- scores GEMM + focal loss ----------------------------------
__global__ void k_scores(const float* __restrict__ box, const float* __restrict__ W,
                         const float* __restrict__ b, const int* __restrict__ labels){
    int wid  = (blockIdx.x*blockDim.x + threadIdx.x) >> 5;
    int lane = threadIdx.x & 31;
    if (wid >= N_) return;
    const float* bx = box + (size_t)wid*R_;
    float xv[32];
    #pragma unroll
    for (int t = 0; t < 32; t++) xv[t] = bx[t*32 + lane];
    int lab = labels[wid];
    float focal = 0.f;
    for (int k = 0; k < C_; k++){
        const float* wr = W + k*R_;
        float s = 0.f;
        #pragma unroll
        for (int t = 0; t < 32; t++) s += xv[t]*wr[t*32 + lane];
        #pragma unroll
        for (int o = 16; o; o >>= 1) s += __shfl_xor_sync(0xffffffffu, s, o);
        s += b[k];
        if (lane == 0){
            g_scores[wid*C_ + k] = s;
            float tt = (k == lab) ? 1.f : 0.f;
            float p  = 1.f/(1.f + expf(-s));
            float ce = fmaxf(s, 0.f) - s*tt + log1pf(expf(-fabsf(s)));
            float pt = p*tt + (1.f - p)*(1.f - tt);
            float at = 0.25f*tt + 0.75f*(1.f - tt);
            float om = 1.f - pt;
            focal += at*ce*om*om;
        }
    }
    if (lane == 0) atomicAdd(&g_cls_sum, focal);
}

// ---------------- covariance: sigma = X^T X / M + eps*I (lower tiles only) --
__global__ void __launch_bounds__(256) k_cov(){
    int t = blockIdx.x;
    int bi = 0;
    while ((((bi+1)*(bi+2)) >> 1) <= t) bi++;
    int bj = t - ((bi*(bi+1)) >> 1);

    __shared__ __align__(16) float As[TK][64];
    __shared__ __align__(16) float Bs[TK][64];

    int tid = threadIdx.x;
    int tx = tid & 15, ty = tid >> 4;
    int ci = bi*64, cj = bj*64;
    int kk  = (tid*4) >> 6;
    int col = (tid*4) & 63;
    const float* pA = g_X + (size_t)kk*R_ + ci + col;
    const float* pB = g_X + (size_t)kk*R_ + cj + col;

    unsigned long long acc[4][2];
    #pragma unroll
    for (int r = 0; r < 4; r++){ acc[r][0] = 0ull; acc[r][1] = 0ull; }

    float4 ra = *(const float4*)pA;
    float4 rb = *(const float4*)pB;
    const int iters = M_/TK;               // 625
    for (int it = 0; it < iters; it++){
        *(float4*)&As[kk][col] = ra;
        *(float4*)&Bs[kk][col] = rb;
        __syncthreads();
        if (it + 1 < iters){               // prefetch next slab during compute
            size_t off = (size_t)(it+1)*TK*R_;
            ra = *(const float4*)(pA + off);
            rb = *(const float4*)(pB + off);
        }
        #pragma unroll
        for (int k = 0; k < TK; k++){
            float4 a4 = *(float4*)&As[k][ty*4];
            float4 b4 = *(float4*)&Bs[k][tx*4];
            unsigned long long bp0 = pack2(b4.x, b4.y);
            unsigned long long bp1 = pack2(b4.z, b4.w);
            float av[4] = {a4.x, a4.y, a4.z, a4.w};
            #pragma unroll
            for (int r = 0; r < 4; r++){
                unsigned long long ap = pack2(av[r], av[r]);
                acc[r][0] = ffma2(ap, bp0, acc[r][0]);
                acc[r][1] = ffma2(ap, bp1, acc[r][1]);
            }
        }
        __syncthreads();
    }
    const float inv = 1.0f/(float)M_;
    #pragma unroll
    for (int r = 0; r < 4; r++){
        float v0, v1, v2, v3;
        unpack2(acc[r][0], v0, v1);
        unpack2(acc[r][1], v2, v3);
        float vals[4] = {v0, v1, v2, v3};
        int gi = ci + ty*4 + r;
        int gj = cj + tx*4;
        #pragma unroll
        for (int c2 = 0; c2 < 4; c2++){
            float v = vals[c2]*inv;
            if (gi == gj + c2) v += 1e-4f;
            g_sigma[(size_t)gi*R_ + gj + c2] = v;
        }
    }
}

// ---------------- Cholesky: blocked, B=64 -----------------------------------
__global__ void k_potrf(int kb){
    __shared__ float A[64][65];
    int tid = threadIdx.x;
    int base = kb*64;
    for (int idx = tid; idx < 4096; idx += 256){
        int i = idx >> 6, j = idx & 63;
        A[i][j] = g_sigma[(size_t)(base+i)*R_ + base + j];
    }
    __syncthreads();
    for (int j = 0; j < 64; j++){
        if (tid == 0) A[j][j] = sqrtf(A[j][j]);
        __syncthreads();
        float dj = A[j][j];
        if (tid < 63 - j){ int i = j + 1 + tid; A[i][j] /= dj; }
        __syncthreads();
        int n = 63 - j;
        for (int t2 = tid; t2 < n*n; t2 += 256){
            int i = j + 1 + t2/n, k = j + 1 + t2%n;
            A[i][k] -= A[i][j]*A[k][j];
        }
        __syncthreads();
    }
    for (int idx = tid; idx < 4096; idx += 256){
        int i = idx >> 6, j = idx & 63;
        if (j <= i) g_sigma[(size_t)(base+i)*R_ + base + j] = A[i][j];
    }
}

__global__ void k_trsm(int kb){
    __shared__ float Ls[64][65];
    __shared__ float Xs[64][65];
    int tid = threadIdx.x;
    int rb = kb + 1 + blockIdx.x;
    int r0 = rb*64, cb = kb*64;
    for (int idx = tid; idx < 4096; idx += 256){
        int i = idx >> 6, j = idx & 63;
        Ls[i][j] = g_sigma[(size_t)(cb+i)*R_ + cb + j];
        Xs[i][j] = g_sigma[(size_t)(r0+i)*R_ + cb + j];
    }
    __syncthreads();
    for (int j = 0; j < 64; j++){
        float invd = 1.0f/Ls[j][j];
        if (tid < 64) Xs[tid][j] *= invd;
        __syncthreads();
        int n = 63 - j;
        for (int t2 = tid; t2 < 64*n; t2 += 256){
            int r = t2/n, k = j + 1 + t2%n;
            Xs[r][k] -= Xs[r][j]*Ls[k][j];
        }
        __syncthreads();
    }
    for (int idx = tid; idx < 4096; idx += 256){
        int i = idx >> 6, j = idx & 63;
        g_sigma[(size_t)(r0+i)*R_ + cb + j] = Xs[i][j];
    }
}

__global__ void k_syrk(int kb){
    __shared__ __align__(16) float Pa[64][68];  // [t][i], padded for f4 align
    __shared__ __align__(16) float Pb[64][68];
    int t = blockIdx.x;
    int a = 0;
    while ((((a+1)*(a+2)) >> 1) <= t) a++;
    int b = t - ((a*(a+1)) >> 1);
    int bi = kb + 1 + a, bj = kb + 1 + b;
    int tid = threadIdx.x;
    int cb = kb*64;
    for (int idx = tid; idx < 4096; idx += 256){
        int i = idx >> 6, tt = idx & 63;
        Pa[tt][i] = g_sigma[(size_t)(bi*64+i)*R_ + cb + tt];
        Pb[tt][i] = g_sigma[(size_t)(bj*64+i)*R_ + cb + tt];
    }
    __syncthreads();
    int tx = tid & 15, ty = tid >> 4;
    float acc[4][4] = {};
    for (int k = 0; k < 64; k++){
        float4 a4 = *(float4*)&Pa[k][ty*4];
        float4 b4 = *(float4*)&Pb[k][tx*4];
        float av[4] = {a4.x, a4.y, a4.z, a4.w};
        float bv[4] = {b4.x, b4.y, b4.z, b4.w};
        #pragma unroll
        for (int r = 0; r < 4; r++)
            #pragma unroll
            for (int c2 = 0; c2 < 4; c2++) acc[r][c2] += av[r]*bv[c2];
    }
    #pragma unroll
    for (int r = 0; r < 4; r++)
        #pragma unroll
        for (int c2 = 0; c2 < 4; c2++)
            g_sigma[(size_t)(bi*64 + ty*4 + r)*R_ + bj*64 + tx*4 + c2] -= acc[r][c2];
}

// ---------------- eps squared norms + per-class argmax ----------------------
__global__ void k_sqnorm(const float* __restrict__ eps){
    int wid  = (blockIdx.x*blockDim.x + threadIdx.x) >> 5;
    int lane = threadIdx.x & 31;
    if (wid >= C_*S_) return;
    const float4* p = (const float4*)(eps + (size_t)wid*R_);
    float s = 0.f;
    #pragma unroll
    for (int t = 0; t < 8; t++){
        float4 v = p[lane + t*32];
        s += v.x*v.x + v.y*v.y + v.z*v.z + v.w*v.w;
    }
    #pragma unroll
    for (int o = 16; o; o >>= 1) s += __shfl_xor_sync(0xffffffffu, s, o);
    if (lane == 0) g_sq[wid] = s;
}

__global__ void k_argmax(){
    int c = blockIdx.x;
    __shared__ float bv[256];
    __shared__ int   bix[256];
    int tid = threadIdx.x;
    float best = -1e30f; int bidx = 0x7fffffff;
    for (int s = tid; s < S_; s += 256){
        float v = g_sq[c*S_ + s];
        if (v > best){ best = v; bidx = s; }       // ascending s -> first max
    }
    bv[tid] = best; bix[tid] = bidx;
    __syncthreads();
    for (int o = 128; o; o >>= 1){
        if (tid < o){
            if (bv[tid+o] > bv[tid] || (bv[tid+o] == bv[tid] && bix[tid+o] < bix[tid])){
                bv[tid] = bv[tid+o]; bix[tid] = bix[tid+o];
            }
        }
        __syncthreads();
    }
    if (tid == 0) g_bestidx[c] = bix[0];
}

// ---------------- vos_samples = mu + eps_sel @ L^T --------------------------
__global__ void k_vos(const float* __restrict__ eps){
    int wid  = (blockIdx.x*256 + threadIdx.x) >> 5;
    int lane = threadIdx.x & 31;
    if (wid >= C_*R_) return;
    int c = wid >> 10, i = wid & 1023;
    const float* sel = eps + ((size_t)c*S_ + g_bestidx[c])*R_;
    const float* Lr  = g_sigma + (size_t)i*R_;
    float s = 0.f;
    for (int j = lane; j <= i; j += 32) s += sel[j]*Lr[j];
    #pragma unroll
    for (int o = 16; o; o >>= 1) s += __shfl_xor_sync(0xffffffffu, s, o);
    if (lane == 0) g_vos[wid] = g_mu[wid] + s;
}

// ---------------- scores_vos = vos @ W^T + b --------------------------------
__global__ void k_svos(const float* __restrict__ W, const float* __restrict__ b){
    int wid  = (blockIdx.x*256 + threadIdx.x) >> 5;
    int lane = threadIdx.x & 31;
    if (wid >= C_*C_) return;
    int c = wid/C_, k = wid%C_;
    const float* v  = g_vos + c*R_;
    const float* wr = W + k*R_;
    float s = 0.f;
    for (int t = lane; t < R_; t += 32) s += v[t]*wr[t];
    #pragma unroll
    for (int o = 16; o; o >>= 1) s += __shfl_xor_sync(0xffffffffu, s, o);
    if (lane == 0) g_svos[wid] = s + b[k];
}

// ---------------- energy -> MLP -> BCE --------------------------------------
__global__ void k_energy(const float* __restrict__ we, const float* __restrict__ W1,
                         const float* __restrict__ b1, const float* __restrict__ W2,
                         const float* __restrict__ b2){
    int wid  = (blockIdx.x*256 + threadIdx.x) >> 5;
    int lane = threadIdx.x & 31;
    if (wid >= N_ + C_) return;
    const float* x = (wid < N_) ? (g_scores + wid*C_) : (g_svos + (wid - N_)*C_);
    float m = -1e30f;
    for (int k = 0; k < C_; k++) m = fmaxf(m, x[k]);
    float ss = 0.f;
    for (int k = 0; k < C_; k++) ss += expf(x[k] - m)*fmaxf(we[k], 0.f);
    float e = m + logf(ss);
    float part = 0.f;
    for (int i = lane; i < 512; i += 32){
        float h = fmaxf(e*W1[i] + b1[i], 0.f);
        part += h*W2[i];
    }
    #pragma unroll
    for (int o = 16; o; o >>= 1) part += __shfl_xor_sync(0xffffffffu, part, o);
    if (lane == 0){
        float l = part + b2[0];
        float y = (wid < N_) ? 1.f : 0.f;
        float bce = fmaxf(l, 0.f) - l*y + log1pf(expf(-fabsf(l)));
        atomicAdd(&g_dist_sum, bce);
    }
}

__global__ void k_final(float* out){
    out[0] = g_cls_sum / (float)N_;
    out[1] = 0.1f * g_dist_sum / (float)(N_ + C_);
}

// ---------------- launch ----------------------------------------------------
extern "C" void kernel_launch(void* const* d_in, const int* in_sizes, int n_in,
                              void* d_out, int out_size){
    (void)in_sizes; (void)n_in; (void)out_size;
    const float* box     = (const float*)d_in[0];
    const int*   labels  = (const int*)  d_in[1];
    const float* idd     = (const float*)d_in[2];
    const int*   counter = (const int*)  d_in[3];
    const float* W       = (const float*)d_in[4];
    const float* b       = (const float*)d_in[5];
    const float* we      = (const float*)d_in[6];
    const float* W1      = (const float*)d_in[7];
    const float* b1      = (const float*)d_in[8];
    const float* W2      = (const float*)d_in[9];
    const float* b2      = (const float*)d_in[10];
    const float* eps     = (const float*)d_in[11];
    float* out = (float*)d_out;

    k_init<<<1, 32>>>();
    k_labelpos<<<1, 512>>>(labels);
    k_mu<<<C_*4, 256>>>(idd, box, counter);
    k_center<<<(M_*R_)/256, 256>>>(idd, box, counter);
    k_scores<<<N_/8, 256>>>(box, W, b, labels);
    k_cov<<<136, 256>>>();
    for (int kb = 0; kb < 16; kb++){
        k_potrf<<<1, 256>>>(kb);
        int nb = 15 - kb;
        if (nb > 0){
            k_trsm<<<nb, 256>>>(kb);
            k_syrk<<<(nb*(nb+1))/2, 256>>>(kb);
        }
    }
    k_sqnorm<<<(C_*S_)/8, 256>>>(eps);
    k_argmax<<<C_, 256>>>();
    k_vos<<<(C_*R_)/8, 256>>>(eps);
    k_svos<<<13, 256>>>(W, b);
    k_energy<<<66, 256>>>(we, W1, b1, W2, b2);
    k_final<<<1, 1>>>(out);
}

// round 10
// speedup vs baseline: 1.9645x; 1.9645x over previous
#include <cuda_runtime.h>
#include <math.h>

#define C_ 10
#define Q_ 1000
#define R_ 1024
#define N_ 512
#define S_ 10000
#define M_ (C_*Q_)      // 10000 rows in x_tilda
#define TK 16           // k-slab for covariance GEMM

typedef unsigned long long u64;

// ---------------- scratch (device globals; no allocation allowed) ----------
__device__ float g_X[M_*R_];          // centered data, 40 MB
__device__ float g_sigma[R_*R_];      // covariance, then (lower) Cholesky L
__device__ float g_mu[C_*R_];
__device__ float g_scores[N_*C_];
__device__ float g_svos[C_*C_];
__device__ float g_vos[C_*R_];
__device__ float g_sq[C_*S_];
__device__ int   g_bestidx[C_];
__device__ int   g_samp[C_*N_];       // ordered sample indices per class
__device__ int   g_kc[C_];
__device__ float g_cls_sum;
__device__ float g_dist_sum;

// ---------------- packed f32x2 helpers (PTX-only FFMA2) ---------------------
__device__ __forceinline__ void ffma2(u64& c, u64 a, u64 b){
    asm("fma.rn.f32x2 %0,%1,%2,%0;":"+l"(c):"l"(a),"l"(b));
}
__device__ __forceinline__ void unpack2(u64 v, float& x, float& y){
    asm("mov.b64 {%0,%1},%2;":"=f"(x),"=f"(y):"l"(v));
}

// ---------------- labelpos + zero accumulators (fused init) -----------------
__global__ void k_labelpos(const int* __restrict__ labels){
    int n = threadIdx.x;
    if (n < C_) g_kc[n] = 0;
    if (n == 30) g_dist_sum = 0.f;
    if (n == 31) g_cls_sum  = 0.f;
    for (int i = n; i < C_*R_; i += 512) g_mu[i] = 0.f;
    __syncthreads();
    int lab = labels[n];
    int pos = 0;
    for (int m = 0; m < n; m++) pos += (labels[m] == lab) ? 1 : 0;
    g_samp[lab*N_ + pos] = n;
    atomicAdd(&g_kc[lab], 1);
}

// source row pointer for post-scatter queue data[c][q][:]
__device__ __forceinline__ const float* qrow(int c, int q,
                                             const float* __restrict__ idd,
                                             const float* __restrict__ box,
                                             int kc, int cnt){
    if (cnt >= Q_){                       // full queue: roll (drop oldest)
        int thr = Q_ - kc;
        if (q < thr) return idd + ((size_t)c*Q_ + q + kc)*R_;
        return box + (size_t)g_samp[c*N_ + (q - thr)]*R_;
    } else {
        if (q >= cnt && q < cnt + kc)
            return box + (size_t)g_samp[c*N_ + (q - cnt)]*R_;
        return idd + ((size_t)c*Q_ + q)*R_;
    }
}

// ---------------- per-class mean (q-split, float4, atomic partials) ---------
__global__ void k_mu(const float* __restrict__ idd, const float* __restrict__ box,
                     const int* __restrict__ counter){
    int c  = blockIdx.x >> 2;
    int qc = blockIdx.x & 3;
    int kc = g_kc[c], cnt = counter[c];
    int r4 = threadIdx.x*4;
    float4 s = make_float4(0.f,0.f,0.f,0.f);
    int q0 = qc*(Q_/4);
    for (int q = q0; q < q0 + Q_/4; q++){
        float4 v = *(const float4*)(qrow(c, q, idd, box, kc, cnt) + r4);
        s.x += v.x; s.y += v.y; s.z += v.z; s.w += v.w;
    }
    float* mp = g_mu + c*R_ + r4;
    atomicAdd(mp+0, s.x*(1.0f/Q_));
    atomicAdd(mp+1, s.y*(1.0f/Q_));
    atomicAdd(mp+2, s.z*(1.0f/Q_));
    atomicAdd(mp+3, s.w*(1.0f/Q_));
}

// ---------------- centered data X (float4) ----------------------------------
__global__ void k_center(const float* __restrict__ idd, const float* __restrict__ box,
                         const int* __restrict__ counter){
    int idx4 = blockIdx.x*blockDim.x + threadIdx.x;   // < M_*R_/4
    int m  = idx4 >> 8;
    int r4 = (idx4 & 255)*4;
    int c = m / Q_;
    int q = m - c*Q_;
    float4 v  = *(const float4*)(qrow(c, q, idd, box, g_kc[c], counter[c]) + r4);
    float4 mu = *(const float4*)(g_mu + c*R_ + r4);
    float4 o = make_float4(v.x-mu.x, v.y-mu.y, v.z-mu.z, v.w-mu.w);
    *(float4*)(g_X + (size_t)m*R_ + r4) = o;
}

// ---------------- covariance: sigma = X^T X / M + eps*I (lower tiles only) --
// A pre-replicated as (v,v) pairs in shared -> FFMA2 operands via LDS.64, no packs.
// Double-buffered, 1 sync per k-slab.
__global__ void __launch_bounds__(256) k_cov(){
    int t = blockIdx.x;
    int bi = 0;
    while ((((bi+1)*(bi+2)) >> 1) <= t) bi++;
    int bj = t - ((bi*(bi+1)) >> 1);

    __shared__ __align__(16) float As2[2][TK][128];   // replicated pairs, 16KB
    __shared__ __align__(16) float Bs [2][TK][64];    // 8KB

    int tid = threadIdx.x;
    int tx = tid & 15, ty = tid >> 4;
    int ci = bi*64, cj = bj*64;
    int kk  = (tid*4) >> 6;
    int col = (tid*4) & 63;
    const float* pA = g_X + (size_t)kk*R_ + ci + col;
    const float* pB = g_X + (size_t)kk*R_ + cj + col;

    u64 acc[4][2];
    #pragma unroll
    for (int r = 0; r < 4; r++){ acc[r][0] = 0ull; acc[r][1] = 0ull; }

    float4 ra = *(const float4*)pA;
    float4 rb = *(const float4*)pB;
    const int iters = M_/TK;               // 625
    int buf = 0;
    for (int it = 0; it < iters; it++){
        float2* da = (float2*)&As2[buf][kk][2*col];
        da[0] = make_float2(ra.x, ra.x);
        da[1] = make_float2(ra.y, ra.y);
        da[2] = make_float2(ra.z, ra.z);
        da[3] = make_float2(ra.w, ra.w);
        *(float4*)&Bs[buf][kk][col] = rb;
        __syncthreads();
        if (it + 1 < iters){               // prefetch next slab during compute
            size_t off = (size_t)(it+1)*TK*R_;
            ra = *(const float4*)(pA + off);
            rb = *(const float4*)(pB + off);
        }
        #pragma unroll
        for (int k = 0; k < TK; k++){
            u64 bp0 = *(const u64*)&Bs[buf][k][tx*4];
            u64 bp1 = *(const u64*)&Bs[buf][k][tx*4 + 2];
            #pragma unroll
            for (int r = 0; r < 4; r++){
                u64 ap = *(const u64*)&As2[buf][k][2*(ty*4 + r)];
                ffma2(acc[r][0], ap, bp0);
                ffma2(acc[r][1], ap, bp1);
            }
        }
        buf ^= 1;
    }
    const float inv = 1.0f/(float)M_;
    #pragma unroll
    for (int r = 0; r < 4; r++){
        float v0, v1, v2, v3;
        unpack2(acc[r][0], v0, v1);
        unpack2(acc[r][1], v2, v3);
        float vals[4] = {v0, v1, v2, v3};
        int gi = ci + ty*4 + r;
        int gj = cj + tx*4;
        #pragma unroll
        for (int c2 = 0; c2 < 4; c2++){
            float v = vals[c2]*inv;
            if (gi == gj + c2) v += 1e-4f;
            g_sigma[(size_t)gi*R_ + gj + c2] = v;
        }
    }
}

// ---------------- scores GEMM + focal loss ----------------------------------
__global__ void k_scores(const float* __restrict__ box, const float* __restrict__ W,
                         const float* __restrict__ b, const int* __restrict__ labels){
    int wid  = (blockIdx.x*blockDim.x + threadIdx.x) >> 5;
    int lane = threadIdx.x & 31;
    if (wid >= N_) return;
    const float* bx = box + (size_t)wid*R_;
    float xv[32];
    #pragma unroll
    for (int t = 0; t < 32; t++) xv[t] = bx[t*32 + lane];
    int lab = labels[wid];
    float focal = 0.f;
    for (int k = 0; k < C_; k++){
        const float* wr = W + k*R_;
        float s = 0.f;
        #pragma unroll
        for (int t = 0; t < 32; t++) s += xv[t]*wr[t*32 + lane];
        #pragma unroll
        for (int o = 16; o; o >>= 1) s += __shfl_xor_sync(0xffffffffu, s, o);
        s += b[k];
        if (lane == 0){
            g_scores[wid*C_ + k] = s;
            float tt = (k == lab) ? 1.f : 0.f;
            float p  = 1.f/(1.f + expf(-s));
            float ce = fmaxf(s, 0.f) - s*tt + log1pf(expf(-fabsf(s)));
            float pt = p*tt + (1.f - p)*(1.f - tt);
            float at = 0.25f*tt + 0.75f*(1.f - tt);
            float om = 1.f - pt;
            focal += at*ce*om*om;
        }
    }
    if (lane == 0) atomicAdd(&g_cls_sum, focal);
}

// ---------------- div-free 64x64 Cholesky (fraction-free elimination) -------
// Eliminate with A[r][k] -= A[r][j]*A[k][j]*rcp(A[j][j]) (1 sync per column),
// then L[i][j] = A[i][j] * rsqrt(A[j][j]) in one parallel pass.
__device__ void potrf64(float (*A)[65]){
    int tid = threadIdx.x;
    int r = tid & 63, q = tid >> 6;          // q in 0..3: column stripe
    for (int j = 0; j < 64; j++){
        __syncthreads();
        if (r > j){
            float inv = __frcp_rn(A[j][j]);
            float arj = A[r][j]*inv;
            int k0 = j + 1 + ((q - (j + 1)) & 3);
            for (int k = k0; k < 64; k += 4)
                A[r][k] -= arj*A[k][j];
        }
    }
    __syncthreads();
    float dv[16];
    #pragma unroll
    for (int u = 0; u < 16; u++){ int j = q*16 + u; dv[u] = A[j][j]; }
    __syncthreads();
    #pragma unroll
    for (int u = 0; u < 16; u++){
        int j = q*16 + u;
        if (r >= j) A[r][j] *= rsqrtf(dv[u]);
    }
    __syncthreads();
}

__global__ void k_potrf0(){
    __shared__ float A[64][65];
    int tid = threadIdx.x;
    for (int idx = tid; idx < 4096; idx += 256){
        int i = idx >> 6, j = idx & 63;
        A[i][j] = g_sigma[(size_t)i*R_ + j];
    }
    potrf64(A);                               // leading sync inside covers load
    for (int idx = tid; idx < 4096; idx += 256){
        int i = idx >> 6, j = idx & 63;
        if (j <= i) g_sigma[(size_t)i*R_ + j] = A[i][j];
    }
}

// ---------------- div-free TRSM: solve X L^T = B for a 64-row tile ----------
// Keep Y = X*diag(L) unscaled during elimination; scale once at writeback.
__global__ void k_trsm(int kb){
    __shared__ float Ls[64][65];
    __shared__ float Ys[64][65];
    int tid = threadIdx.x;
    int rb = kb + 1 + blockIdx.x;
    int r0 = rb*64, cb = kb*64;
    for (int idx = tid; idx < 4096; idx += 256){
        int i = idx >> 6, j = idx & 63;
        Ls[i][j] = g_sigma[(size_t)(cb+i)*R_ + cb + j];
        Ys[i][j] = g_sigma[(size_t)(r0+i)*R_ + cb + j];
    }
    int r = tid & 63, q = tid >> 6;
    for (int j = 0; j < 64; j++){
        __syncthreads();
        float inv = __frcp_rn(Ls[j][j]);
        float yr = Ys[r][j]*inv;
        int k0 = j + 1 + ((q - (j + 1)) & 3);
        for (int k = k0; k < 64; k += 4)
            Ys[r][k] -= yr*Ls[k][j];
    }
    __syncthreads();
    #pragma unroll
    for (int u = 0; u < 16; u++){
        int j = q*16 + u;
        g_sigma[(size_t)(r0+r)*R_ + cb + j] = Ys[r][j]*__frcp_rn(Ls[j][j]);
    }
}

// ---------------- trailing SYRK update; block 0 also potrf's next diag tile -
__global__ void __launch_bounds__(256) k_syrkpotrf(int kb){
    __shared__ __align__(16) float Pa[64][68];
    __shared__ __align__(16) float Pb[64][68];
    int t = blockIdx.x;
    int a = 0;
    while ((((a+1)*(a+2)) >> 1) <= t) a++;
    int b = t - ((a*(a+1)) >> 1);
    int bi = kb + 1 + a, bj = kb + 1 + b;
    int tid = threadIdx.x;
    int cb = kb*64;
    for (int idx = tid; idx < 4096; idx += 256){
        int i = idx >> 6, tt = idx & 63;
        Pa[tt][i] = g_sigma[(size_t)(bi*64+i)*R_ + cb + tt];
        Pb[tt][i] = g_sigma[(size_t)(bj*64+i)*R_ + cb + tt];
    }
    __syncthreads();
    int tx = tid & 15, ty = tid >> 4;
    float acc[4][4] = {};
    for (int k = 0; k < 64; k++){
        float4 a4 = *(float4*)&Pa[k][ty*4];
        float4 b4 = *(float4*)&Pb[k][tx*4];
        float av[4] = {a4.x, a4.y, a4.z, a4.w};
        float bv[4] = {b4.x, b4.y, b4.z, b4.w};
        #pragma unroll
        for (int r = 0; r < 4; r++)
            #pragma unroll
            for (int c2 = 0; c2 < 4; c2++) acc[r][c2] += av[r]*bv[c2];
    }
    if (t != 0){
        #pragma unroll
        for (int r = 0; r < 4; r++)
            #pragma unroll
            for (int c2 = 0; c2 < 4; c2++)
                g_sigma[(size_t)(bi*64 + ty*4 + r)*R_ + bj*64 + tx*4 + c2] -= acc[r][c2];
    } else {
        // diagonal tile of next panel: update in shared, factor, write L
        __syncthreads();                       // done reading Pa before overwrite
        float (*A)[65] = (float(*)[65])Pa;     // reuse Pa storage (4352 >= 4160)
        #pragma unroll
        for (int r = 0; r < 4; r++)
            #pragma unroll
            for (int c2 = 0; c2 < 4; c2++)
                A[ty*4 + r][tx*4 + c2] =
                    g_sigma[(size_t)(bi*64 + ty*4 + r)*R_ + bj*64 + tx*4 + c2] - acc[r][c2];
        potrf64(A);
        int base = (kb + 1)*64;
        for (int idx = tid; idx < 4096; idx += 256){
            int i = idx >> 6, j = idx & 63;
            if (j <= i) g_sigma[(size_t)(base+i)*R_ + base + j] = A[i][j];
        }
    }
}

// ---------------- eps squared norms + per-class argmax ----------------------
__global__ void k_sqnorm(const float* __restrict__ eps){
    int wid  = (blockIdx.x*blockDim.x + threadIdx.x) >> 5;
    int lane = threadIdx.x & 31;
    if (wid >= C_*S_) return;
    const float4* p = (const float4*)(eps + (size_t)wid*R_);
    float s = 0.f;
    #pragma unroll
    for (int t = 0; t < 8; t++){
        float4 v = p[lane + t*32];
        s += v.x*v.x + v.y*v.y + v.z*v.z + v.w*v.w;
    }
    #pragma unroll
    for (int o = 16; o; o >>= 1) s += __shfl_xor_sync(0xffffffffu, s, o);
    if (lane == 0) g_sq[wid] = s;
}

__global__ void k_argmax(){
    int c = blockIdx.x;
    __shared__ float bv[256];
    __shared__ int   bix[256];
    int tid = threadIdx.x;
    float best = -1e30f; int bidx = 0x7fffffff;
    for (int s = tid; s < S_; s += 256){
        float v = g_sq[c*S_ + s];
        if (v > best){ best = v; bidx = s; }       // ascending s -> first max
    }
    bv[tid] = best; bix[tid] = bidx;
    __syncthreads();
    for (int o = 128; o; o >>= 1){
        if (tid < o){
            if (bv[tid+o] > bv[tid] || (bv[tid+o] == bv[tid] && bix[tid+o] < bix[tid])){
                bv[tid] = bv[tid+o]; bix[tid] = bix[tid+o];
            }
        }
        __syncthreads();
    }
    if (tid == 0) g_bestidx[c] = bix[0];
}

// ---------------- vos_samples = mu + eps_sel @ L^T --------------------------
__global__ void k_vos(const float* __restrict__ eps){
    int wid  = (blockIdx.x*256 + threadIdx.x) >> 5;
    int lane = threadIdx.x & 31;
    if (wid >= C_*R_) return;
    int c = wid >> 10, i = wid & 1023;
    const float* sel = eps + ((size_t)c*S_ + g_bestidx[c])*R_;
    const float* Lr  = g_sigma + (size_t)i*R_;
    float s = 0.f;
    for (int j = lane; j <= i; j += 32) s += sel[j]*Lr[j];
    #pragma unroll
    for (int o = 16; o; o >>= 1) s += __shfl_xor_sync(0xffffffffu, s, o);
    if (lane == 0) g_vos[wid] = g_mu[wid] + s;
}

// ---------------- scores_vos = vos @ W^T + b --------------------------------
__global__ void k_svos(const float* __restrict__ W, const float* __restrict__ b){
    int wid  = (blockIdx.x*256 + threadIdx.x) >> 5;
    int lane = threadIdx.x & 31;
    if (wid >= C_*C_) return;
    int c = wid/C_, k = wid%C_;
    const float* v  = g_vos + c*R_;
    const float* wr = W + k*R_;
    float s = 0.f;
    for (int t = lane; t < R_; t += 32) s += v[t]*wr[t];
    #pragma unroll
    for (int o = 16; o; o >>= 1) s += __shfl_xor_sync(0xffffffffu, s, o);
    if (lane == 0) g_svos[wid] = s + b[k];
}

// ---------------- energy -> MLP -> BCE --------------------------------------
__global__ void k_energy(const float* __restrict__ we, const float* __restrict__ W1,
                         const float* __restrict__ b1, const float* __restrict__ W2,
                         const float* __restrict__ b2){
    int wid  = (blockIdx.x*256 + threadIdx.x) >> 5;
    int lane = threadIdx.x & 31;
    if (wid >= N_ + C_) return;
    const float* x = (wid < N_) ? (g_scores + wid*C_) : (g_svos + (wid - N_)*C_);
    float m = -1e30f;
    for (int k = 0; k < C_; k++) m = fmaxf(m, x[k]);
    float ss = 0.f;
    for (int k = 0; k < C_; k++) ss += expf(x[k] - m)*fmaxf(we[k], 0.f);
    float e = m + logf(ss);
    float part = 0.f;
    for (int i = lane; i < 512; i += 32){
        float h = fmaxf(e*W1[i] + b1[i], 0.f);
        part += h*W2[i];
    }
    #pragma unroll
    for (int o = 16; o; o >>= 1) part += __shfl_xor_sync(0xffffffffu, part, o);
    if (lane == 0){
        float l = part + b2[0];
        float y = (wid < N_) ? 1.f : 0.f;
        float bce = fmaxf(l, 0.f) - l*y + log1pf(expf(-fabsf(l)));
        atomicAdd(&g_dist_sum, bce);
    }
}

__global__ void k_final(float* out){
    out[0] = g_cls_sum / (float)N_;
    out[1] = 0.1f * g_dist_sum / (float)(N_ + C_);
}

// ---------------- launch ----------------------------------------------------
extern "C" void kernel_launch(void* const* d_in, const int* in_sizes, int n_in,
                              void* d_out, int out_size){
    (void)in_sizes; (void)n_in; (void)out_size;
    const float* box     = (const float*)d_in[0];
    const int*   labels  = (const int*)  d_in[1];
    const float* idd     = (const float*)d_in[2];
    const int*   counter = (const int*)  d_in[3];
    const float* W       = (const float*)d_in[4];
    const float* b       = (const float*)d_in[5];
    const float* we      = (const float*)d_in[6];
    const float* W1      = (const float*)d_in[7];
    const float* b1      = (const float*)d_in[8];
    const float* W2      = (const float*)d_in[9];
    const float* b2      = (const float*)d_in[10];
    const float* eps     = (const float*)d_in[11];
    float* out = (float*)d_out;

    // order chosen so the ncu single-capture slot lands on k_cov
    k_labelpos<<<1, 512>>>(labels);                       // launch 0
    k_mu<<<C_*4, 256>>>(idd, box, counter);               // launch 1
    k_center<<<(M_*R_)/1024, 256>>>(idd, box, counter);   // launch 2 (float4)
    k_cov<<<136, 256>>>();                                // launch 3  <-- capture
    k_scores<<<N_/8, 256>>>(box, W, b, labels);

    k_potrf0<<<1, 256>>>();
    for (int kb = 0; kb < 15; kb++){
        int nb = 15 - kb;
        k_trsm<<<nb, 256>>>(kb);
        k_syrkpotrf<<<(nb*(nb+1))/2, 256>>>(kb);          // block 0 potrfs panel kb+1
    }

    k_sqnorm<<<(C_*S_)/8, 256>>>(eps);
    k_argmax<<<C_, 256>>>();
    k_vos<<<(C_*R_)/8, 256>>>(eps);
    k_svos<<<13, 256>>>(W, b);
    k_energy<<<66, 256>>>(we, W1, b1, W2, b2);
    k_final<<<1, 1>>>(out);
}

// round 14
// speedup vs baseline: 1.9694x; 1.0025x over previous
#include <cuda_runtime.h>
#include <math.h>

#define C_ 10
#define Q_ 1000
#define R_ 1024
#define N_ 512
#define S_ 10000
#define M_ (C_*Q_)      // 10000 rows in x_tilda
#define TK 16           // k-slab for covariance GEMM
#define GCHOL 120       // persistent Cholesky grid (>= max syrk tiles = 120)

typedef unsigned long long u64;

// ---------------- scratch (device globals; no allocation allowed) ----------
__device__ float g_sigma[R_*R_];      // covariance, then (lower) Cholesky L
__device__ float g_mu[C_*R_];
__device__ u64   g_best[C_];          // packed (sqnorm bits << 32) | (S-1-idx)
__device__ int   g_samp[C_*N_];       // ordered sample indices per class
__device__ int   g_kc[C_];
__device__ const float* g_rowp[M_];   // row pointers of post-scatter data
__device__ float g_cls_sum;
__device__ float g_dist_sum;
__device__ unsigned int g_barctr;     // grid barrier counter (zeroed per call)

// ---------------- packed f32x2 helpers (PTX-only FFMA2) ---------------------
__device__ __forceinline__ void ffma2(u64& c, u64 a, u64 b){
    asm("fma.rn.f32x2 %0,%1,%2,%0;":"+l"(c):"l"(a),"l"(b));
}
__device__ __forceinline__ void unpack2(u64 v, float& x, float& y){
    asm("mov.b64 {%0,%1},%2;":"=f"(x),"=f"(y):"l"(v));
}

// ---------------- labelpos + init + row-pointer table -----------------------
__global__ void k_labelpos(const int* __restrict__ labels,
                           const float* __restrict__ idd,
                           const float* __restrict__ box){
    __shared__ int sh_base[C_+1];
    int n = threadIdx.x;
    if (n < C_){ g_kc[n] = 0; g_best[n] = 0ull; }
    if (n == 30) g_dist_sum = 0.f;
    if (n == 31) g_cls_sum  = 0.f;
    if (n == 32) g_barctr   = 0u;
    for (int i = n; i < C_*R_; i += N_) g_mu[i] = 0.f;
    __syncthreads();
    int lab = labels[n];
    int pos = 0;
    for (int m = 0; m < n; m++) pos += (labels[m] == lab) ? 1 : 0;
    g_samp[lab*N_ + pos] = n;
    atomicAdd(&g_kc[lab], 1);
    __syncthreads();
    if (n == 0){
        int bacc = 0;
        for (int c = 0; c < C_; c++){ sh_base[c] = bacc; bacc += Q_ - g_kc[c]; }
        sh_base[C_] = bacc;                       // = M_ - N_
    }
    __syncthreads();
    for (int c = 0; c < C_; c++){
        int kc = g_kc[c], cnt = Q_ - kc, base = sh_base[c];
        for (int i = n; i < cnt; i += N_)
            g_rowp[base + i] = idd + ((size_t)(c*Q_ + kc + i))*R_;
    }
    g_rowp[sh_base[C_] + n] = box + (size_t)n*R_;
}

// source row pointer for post-scatter queue data[c][q][:] (mu only)
__device__ __forceinline__ const float* qrow(int c, int q,
                                             const float* __restrict__ idd,
                                             const float* __restrict__ box,
                                             int kc, int cnt){
    if (cnt >= Q_){
        int thr = Q_ - kc;
        if (q < thr) return idd + ((size_t)c*Q_ + q + kc)*R_;
        return box + (size_t)g_samp[c*N_ + (q - thr)]*R_;
    } else {
        if (q >= cnt && q < cnt + kc)
            return box + (size_t)g_samp[c*N_ + (q - cnt)]*R_;
        return idd + ((size_t)c*Q_ + q)*R_;
    }
}

// ---------------- per-class mean (q-split, float4) + zero sigma -------------
__global__ void k_mu(const float* __restrict__ idd, const float* __restrict__ box,
                     const int* __restrict__ counter){
    // zero g_sigma (needed: k_cov accumulates with atomics)
    float4 z = make_float4(0.f,0.f,0.f,0.f);
    for (int i = blockIdx.x*blockDim.x + threadIdx.x; i < R_*R_/4;
         i += gridDim.x*blockDim.x)
        ((float4*)g_sigma)[i] = z;

    int c  = blockIdx.x >> 2;
    int qc = blockIdx.x & 3;
    int kc = g_kc[c], cnt = counter[c];
    int r4 = threadIdx.x*4;
    float4 s = make_float4(0.f,0.f,0.f,0.f);
    int q0 = qc*(Q_/4);
    for (int q = q0; q < q0 + Q_/4; q++){
        float4 v = *(const float4*)(qrow(c, q, idd, box, kc, cnt) + r4);
        s.x += v.x; s.y += v.y; s.z += v.z; s.w += v.w;
    }
    float* mp = g_mu + c*R_ + r4;
    atomicAdd(mp+0, s.x*(1.0f/Q_));
    atomicAdd(mp+1, s.y*(1.0f/Q_));
    atomicAdd(mp+2, s.z*(1.0f/Q_));
    atomicAdd(mp+3, s.w*(1.0f/Q_));
}

// ---------------- eps squared norms + fused per-class argmax ----------------
// grid = C_*40 blocks; block handles 250 rows of one class; packed atomicMax.
__global__ void k_sqnorm(const float* __restrict__ eps){
    __shared__ float bs[8]; __shared__ int bi_[8];
    int c     = blockIdx.x / 40;
    int chunk = blockIdx.x % 40;
    int w = threadIdx.x >> 5, lane = threadIdx.x & 31;
    float best = -1.f; int bidx = 0;
    for (int i = 0; i < 32; i++){
        int rr = w + 8*i;
        if (rr >= 250) break;
        int srow = chunk*250 + rr;
        const float4* p = (const float4*)(eps + ((size_t)c*S_ + srow)*R_);
        float s = 0.f;
        #pragma unroll
        for (int t = 0; t < 8; t++){
            float4 v = p[lane + t*32];
            s += v.x*v.x + v.y*v.y + v.z*v.z + v.w*v.w;
        }
        #pragma unroll
        for (int o = 16; o; o >>= 1) s += __shfl_xor_sync(0xffffffffu, s, o);
        if (s > best){ best = s; bidx = srow; }   // ascending -> first max kept
    }
    if (lane == 0){ bs[w] = best; bi_[w] = bidx; }
    __syncthreads();
    if (threadIdx.x == 0){
        float bb = bs[0]; int ii = bi_[0];
        for (int k = 1; k < 8; k++)
            if (bs[k] > bb || (bs[k] == bb && bi_[k] < ii)){ bb = bs[k]; ii = bi_[k]; }
        u64 packed = ((u64)__float_as_uint(bb) << 32) | (u64)(unsigned)(S_ - 1 - ii);
        atomicMax(&g_best[c], packed);            // order-independent, tie->min idx
    }
}

// ---------------- covariance: sigma = (1/M) X^T X + corr, lower tiles -------
// Direct gather via g_rowp (no centered copy). K split in 2 (272 CTAs, 2/SM).
// A replicated pairs -> LDS.128; B -> LDS.128 as u64x2. 3 LDS / 8 FFMA2 per k.
__global__ void __launch_bounds__(256) k_cov(){
    int t     = blockIdx.x >> 1;
    int chunk = blockIdx.x & 1;
    int bi = 0;
    while ((((bi+1)*(bi+2)) >> 1) <= t) bi++;
    int bj = t - ((bi*(bi+1)) >> 1);

    __shared__ __align__(16) float As2[2][TK][128];   // replicated (v,v) pairs
    __shared__ __align__(16) float Bs [2][TK][64];

    int tid = threadIdx.x;
    int tx = tid & 15, ty = tid >> 4;
    int ci = bi*64, cj = bj*64;
    int kk  = (tid*4) >> 6;
    int col = (tid*4) & 63;

    int it0 = chunk ? 313 : 0;
    int it1 = chunk ? 625 : 313;

    u64 acc[4][2];
    #pragma unroll
    for (int r = 0; r < 4; r++){ acc[r][0] = 0ull; acc[r][1] = 0ull; }

    const float* rp = g_rowp[it0*TK + kk];
    float4 ra = *(const float4*)(rp + ci + col);
    float4 rb = *(const float4*)(rp + cj + col);

    int buf = 0;
    for (int it = it0; it < it1; it++){
        *(float4*)&As2[buf][kk][2*col]     = make_float4(ra.x, ra.x, ra.y, ra.y);
        *(float4*)&As2[buf][kk][2*col + 4] = make_float4(ra.z, ra.z, ra.w, ra.w);
        *(float4*)&Bs[buf][kk][col] = rb;
        __syncthreads();
        if (it + 1 < it1){
            rp = g_rowp[(it+1)*TK + kk];
            ra = *(const float4*)(rp + ci + col);
            rb = *(const float4*)(rp + cj + col);
        }
        #pragma unroll
        for (int k = 0; k < TK; k++){
            ulonglong2 a01 = *(const ulonglong2*)&As2[buf][k][2*(ty*4)];
            ulonglong2 a23 = *(const ulonglong2*)&As2[buf][k][2*(ty*4) + 4];
            ulonglong2 b01 = *(const ulonglong2*)&Bs[buf][k][tx*4];
            ffma2(acc[0][0], a01.x, b01.x); ffma2(acc[0][1], a01.x, b01.y);
            ffma2(acc[1][0], a01.y, b01.x); ffma2(acc[1][1], a01.y, b01.y);
            ffma2(acc[2][0], a23.x, b01.x); ffma2(acc[2][1], a23.x, b01.y);
            ffma2(acc[3][0], a23.y, b01.x); ffma2(acc[3][1], a23.y, b01.y);
        }
        buf ^= 1;
    }

    const float inv = 1.0f/(float)M_;
    #pragma unroll
    for (int r = 0; r < 4; r++){
        float v0, v1, v2, v3;
        unpack2(acc[r][0], v0, v1);
        unpack2(acc[r][1], v2, v3);
        float vals[4] = {v0, v1, v2, v3};
        int gi = ci + ty*4 + r;
        #pragma unroll
        for (int c2 = 0; c2 < 4; c2++){
            int gj = cj + tx*4 + c2;
            float v = vals[c2]*inv;
            if (chunk == 0){
                // mean correction: -(Q/M) * sum_c mu[c][gi]*mu[c][gj], + eps eye
                float corr = 0.f;
                #pragma unroll
                for (int cc = 0; cc < C_; cc++)
                    corr += g_mu[cc*R_ + gi]*g_mu[cc*R_ + gj];
                v -= corr*((float)Q_*inv);
                if (gi == gj) v += 1e-4f;
            }
            atomicAdd(&g_sigma[(size_t)gi*R_ + gj], v);   // exactly 2 adds/elem
        }
    }
}

// ---------------- scores GEMM + focal loss + fused energy/MLP/BCE -----------
__global__ void k_scores(const float* __restrict__ box, const float* __restrict__ W,
                         const float* __restrict__ bb, const int* __restrict__ labels,
                         const float* __restrict__ we, const float* __restrict__ W1,
                         const float* __restrict__ b1, const float* __restrict__ W2,
                         const float* __restrict__ b2){
    int wid  = (blockIdx.x*blockDim.x + threadIdx.x) >> 5;
    int lane = threadIdx.x & 31;
    if (wid >= N_) return;
    const float* bx = box + (size_t)wid*R_;
    float xv[32];
    #pragma unroll
    for (int t = 0; t < 32; t++) xv[t] = bx[t*32 + lane];
    int lab = labels[wid];
    float focal = 0.f;
    float sk[C_];
    #pragma unroll
    for (int k = 0; k < C_; k++){
        const float* wr = W + k*R_;
        float s = 0.f;
        #pragma unroll
        for (int t = 0; t < 32; t++) s += xv[t]*wr[t*32 + lane];
        #pragma unroll
        for (int o = 16; o; o >>= 1) s += __shfl_xor_sync(0xffffffffu, s, o);
        s += bb[k];                       // butterfly: every lane has full sum
        sk[k] = s;
        if (lane == 0){
            float tt = (k == lab) ? 1.f : 0.f;
            float p  = 1.f/(1.f + expf(-s));
            float ce = fmaxf(s, 0.f) - s*tt + log1pf(expf(-fabsf(s)));
            float pt = p*tt + (1.f - p)*(1.f - tt);
            float at = 0.25f*tt + 0.75f*(1.f - tt);
            float om = 1.f - pt;
            focal += at*ce*om*om;
        }
    }
    if (lane == 0) atomicAdd(&g_cls_sum, focal);
    // energy -> MLP -> BCE (y = 1) for this row
    float m = sk[0];
    #pragma unroll
    for (int k = 1; k < C_; k++) m = fmaxf(m, sk[k]);
    float ss = 0.f;
    #pragma unroll
    for (int k = 0; k < C_; k++) ss += expf(sk[k] - m)*fmaxf(we[k], 0.f);
    float e = m + logf(ss);
    float part = 0.f;
    for (int i = lane; i < 512; i += 32)
        part += fmaxf(e*W1[i] + b1[i], 0.f)*W2[i];
    #pragma unroll
    for (int o = 16; o; o >>= 1) part += __shfl_xor_sync(0xffffffffu, part, o);
    if (lane == 0){
        float l = part + b2[0];
        float bce = fmaxf(l, 0.f) - l + log1pf(expf(-fabsf(l)));
        atomicAdd(&g_dist_sum, bce);
    }
}

// ---------------- persistent Cholesky: one kernel, manual grid barrier ------
__device__ __forceinline__ void gridbar(unsigned int target){
    __threadfence();                       // publish my writes (L1 write-through + fence)
    __syncthreads();
    if (threadIdx.x == 0){
        atomicAdd(&g_barctr, 1u);
        while (*(volatile unsigned int*)&g_barctr < target) __nanosleep(128);
        __threadfence();                   // CCTL.IVALL: invalidate this SM's L1
    }
    __syncthreads();
}

// div-free fraction-free 64x64 potrf on pitch-65 shared tile
__device__ void potrf64p(float (*A)[65]){
    int tid = threadIdx.x;
    int r = tid & 63, q = tid >> 6;
    for (int j = 0; j < 64; j++){
        __syncthreads();
        if (r > j){
            float inv = __frcp_rn(A[j][j]);
            float arj = A[r][j]*inv;
            int k0 = j + 1 + ((q - (j + 1)) & 3);
            for (int k = k0; k < 64; k += 4)
                A[r][k] -= arj*A[k][j];
        }
    }
    __syncthreads();
    float dv[16];
    #pragma unroll
    for (int u = 0; u < 16; u++){ int j = q*16 + u; dv[u] = A[j][j]; }
    __syncthreads();
    #pragma unroll
    for (int u = 0; u < 16; u++){
        int j = q*16 + u;
        if (r >= j) A[r][j] *= rsqrtf(dv[u]);
    }
    __syncthreads();
}

__global__ void __launch_bounds__(256) k_chol(){
    __shared__ __align__(16) float S0[64][68];
    __shared__ __align__(16) float S1[64][68];
    int cta = blockIdx.x;
    int tid = threadIdx.x;
    unsigned int tgt = 0;

    if (cta == 0){                                        // potrf panel 0
        float (*A)[65] = (float(*)[65])S0;
        for (int idx = tid; idx < 4096; idx += 256){
            int i = idx >> 6, j = idx & 63;
            A[i][j] = g_sigma[(size_t)i*R_ + j];
        }
        potrf64p(A);
        for (int idx = tid; idx < 4096; idx += 256){
            int i = idx >> 6, j = idx & 63;
            if (j <= i) g_sigma[(size_t)i*R_ + j] = A[i][j];
        }
    }
    tgt += GCHOL; gridbar(tgt);

    for (int kb = 0; kb < 15; kb++){
        int nb = 15 - kb;
        if (cta < nb){                                    // TRSM tile (div-free)
            float (*Ls)[65] = (float(*)[65])S0;
            float (*Ys)[65] = (float(*)[65])S1;
            int rb = kb + 1 + cta, r0 = rb*64, cb = kb*64;
            for (int idx = tid; idx < 4096; idx += 256){
                int i = idx >> 6, j = idx & 63;
                Ls[i][j] = g_sigma[(size_t)(cb+i)*R_ + cb + j];
                Ys[i][j] = g_sigma[(size_t)(r0+i)*R_ + cb + j];
            }
            int r = tid & 63, q = tid >> 6;
            for (int j = 0; j < 64; j++){
                __syncthreads();
                float inv = __frcp_rn(Ls[j][j]);
                float yr = Ys[r][j]*inv;
                int k0 = j + 1 + ((q - (j + 1)) & 3);
                for (int k = k0; k < 64; k += 4)
                    Ys[r][k] -= yr*Ls[k][j];
            }
            __syncthreads();
            #pragma unroll
            for (int u = 0; u < 16; u++){
                int j = q*16 + u;
                g_sigma[(size_t)(r0+r)*R_ + cb + j] = Ys[r][j]*__frcp_rn(Ls[j][j]);
            }
        }
        tgt += GCHOL; gridbar(tgt);

        int ntile = nb*(nb+1)/2;
        if (cta < ntile){                                 // SYRK (+potrf on tile 0)
            int a = 0;
            while ((((a+1)*(a+2)) >> 1) <= cta) a++;
            int b = cta - ((a*(a+1)) >> 1);
            int bi = kb + 1 + a, bj = kb + 1 + b;
            int cb = kb*64;
            for (int idx = tid; idx < 4096; idx += 256){
                int i = idx >> 6, tt = idx & 63;
                S0[tt][i] = g_sigma[(size_t)(bi*64+i)*R_ + cb + tt];
                S1[tt][i] = g_sigma[(size_t)(bj*64+i)*R_ + cb + tt];
            }
            __syncthreads();
            int tx = tid & 15, ty = tid >> 4;
            float acc[4][4] = {};
            for (int k = 0; k < 64; k++){
                float4 a4 = *(float4*)&S0[k][ty*4];
                float4 b4 = *(float4*)&S1[k][tx*4];
                float av[4] = {a4.x, a4.y, a4.z, a4.w};
                float bv[4] = {b4.x, b4.y, b4.z, b4.w};
                #pragma unroll
                for (int r = 0; r < 4; r++)
                    #pragma unroll
                    for (int c2 = 0; c2 < 4; c2++) acc[r][c2] += av[r]*bv[c2];
            }
            if (cta != 0){
                #pragma unroll
                for (int r = 0; r < 4; r++)
                    #pragma unroll
                    for (int c2 = 0; c2 < 4; c2++)
                        g_sigma[(size_t)(bi*64 + ty*4 + r)*R_ + bj*64 + tx*4 + c2]
                            -= acc[r][c2];
            } else {                                      // next diag: update+potrf
                __syncthreads();
                float (*A)[65] = (float(*)[65])S0;
                #pragma unroll
                for (int r = 0; r < 4; r++)
                    #pragma unroll
                    for (int c2 = 0; c2 < 4; c2++)
                        A[ty*4 + r][tx*4 + c2] =
                            g_sigma[(size_t)(bi*64 + ty*4 + r)*R_ + bj*64 + tx*4 + c2]
                            - acc[r][c2];
                potrf64p(A);
                int base = (kb + 1)*64;
                for (int idx = tid; idx < 4096; idx += 256){
                    int i = idx >> 6, j = idx & 63;
                    if (j <= i) g_sigma[(size_t)(base+i)*R_ + base + j] = A[i][j];
                }
            }
        }
        tgt += GCHOL; gridbar(tgt);
    }
}

// ---------------- vos + scores_vos + energy/BCE, one block per class --------
__global__ void k_vostail(const float* __restrict__ eps, const float* __restrict__ W,
                          const float* __restrict__ bb, const float* __restrict__ we,
                          const float* __restrict__ W1, const float* __restrict__ b1,
                          const float* __restrict__ W2, const float* __restrict__ b2){
    __shared__ float vos_s[R_];
    __shared__ float svos_s[C_];
    int c = blockIdx.x;
    int w = threadIdx.x >> 5, lane = threadIdx.x & 31;
    int idx = S_ - 1 - (int)(unsigned)(g_best[c] & 0xffffffffull);
    const float* sel = eps + ((size_t)c*S_ + idx)*R_;
    for (int r = w; r < R_; r += 8){
        const float* Lr = g_sigma + (size_t)r*R_;
        float s = 0.f;
        for (int j = lane; j <= r; j += 32) s += sel[j]*Lr[j];
        #pragma unroll
        for (int o = 16; o; o >>= 1) s += __shfl_xor_sync(0xffffffffu, s, o);
        if (lane == 0) vos_s[r] = g_mu[c*R_ + r] + s;
    }
    __syncthreads();
    for (int k = w; k < C_; k += 8){
        const float* wr = W + k*R_;
        float s = 0.f;
        for (int i = lane; i < R_; i += 32) s += vos_s[i]*wr[i];
        #pragma unroll
        for (int o = 16; o; o >>= 1) s += __shfl_xor_sync(0xffffffffu, s, o);
        if (lane == 0) svos_s[k] = s + bb[k];
    }
    __syncthreads();
    if (w == 0){
        float m = svos_s[0];
        #pragma unroll
        for (int k = 1; k < C_; k++) m = fmaxf(m, svos_s[k]);
        float ss = 0.f;
        #pragma unroll
        for (int k = 0; k < C_; k++) ss += expf(svos_s[k] - m)*fmaxf(we[k], 0.f);
        float e = m + logf(ss);
        float part = 0.f;
        for (int i = lane; i < 512; i += 32)
            part += fmaxf(e*W1[i] + b1[i], 0.f)*W2[i];
        #pragma unroll
        for (int o = 16; o; o >>= 1) part += __shfl_xor_sync(0xffffffffu, part, o);
        if (lane == 0){
            float l = part + b2[0];
            float bce = fmaxf(l, 0.f) + log1pf(expf(-fabsf(l)));   // y = 0
            atomicAdd(&g_dist_sum, bce);
        }
    }
}

__global__ void k_final(float* out){
    out[0] = g_cls_sum / (float)N_;
    out[1] = 0.1f * g_dist_sum / (float)(N_ + C_);
}

// ---------------- launch ----------------------------------------------------
extern "C" void kernel_launch(void* const* d_in, const int* in_sizes, int n_in,
                              void* d_out, int out_size){
    (void)in_sizes; (void)n_in; (void)out_size;
    const float* box     = (const float*)d_in[0];
    const int*   labels  = (const int*)  d_in[1];
    const float* idd     = (const float*)d_in[2];
    const int*   counter = (const int*)  d_in[3];
    const float* W       = (const float*)d_in[4];
    const float* b       = (const float*)d_in[5];
    const float* we      = (const float*)d_in[6];
    const float* W1      = (const float*)d_in[7];
    const float* b1      = (const float*)d_in[8];
    const float* W2      = (const float*)d_in[9];
    const float* b2      = (const float*)d_in[10];
    const float* eps     = (const float*)d_in[11];
    float* out = (float*)d_out;

    // 8 launches total; index 3 (ncu capture slot) = k_cov
    k_labelpos<<<1, N_>>>(labels, idd, box);
    k_mu<<<C_*4, 256>>>(idd, box, counter);
    k_sqnorm<<<C_*40, 256>>>(eps);
    k_cov<<<272, 256>>>();
    k_scores<<<N_/8, 256>>>(box, W, b, labels, we, W1, b1, W2, b2);
    k_chol<<<GCHOL, 256>>>();
    k_vostail<<<C_, 256>>>(eps, W, b, we, W1, b1, W2, b2);
    k_final<<<1, 1>>>(out);
}